// round 3
// baseline (speedup 1.0000x reference)
#include <cuda_runtime.h>

#define TF 481
#define NK 48
#define TILE 112
#define CST 962           // 2*TF (re,im interleaved per slot)
#define NTHREADS 192

// Shared memory plan (floats):
//   covsm : 8 slots * CST   (slots 0-5: pair (re,im); 6: diag0,diag1; 7: diag2,diag3)
//   adjsm : 8 slots * CST   (same layout, phase-adjusted)
//   bsmR  : TILE*NK, bsmI : TILE*NK   (band tile)
//   c2sm  : 512 (transposed c2pv: real [c*16+p], imag at +256)
#define SMEM_FLOATS (8*CST*2 + TILE*NK*2 + 512)

__global__ __launch_bounds__(NTHREADS) void pv_stage1(
    const float* __restrict__ binsR, const float* __restrict__ binsI,
    const float* __restrict__ bandR, const float* __restrict__ bandI,
    const float* __restrict__ c2r,  const float* __restrict__ c2i,
    float* __restrict__ out)
{
    extern __shared__ float sm[];
    float* covsm = sm;
    float* adjsm = covsm + 8*CST;
    float* bsmR  = adjsm + 8*CST;
    float* bsmI  = bsmR + TILE*NK;
    float* c2sm  = bsmI + TILE*NK;

    const int bt  = blockIdx.x;          // b*1024 + t
    const int tid = threadIdx.x;
    const int b   = bt >> 10;
    const int t   = bt & 1023;

    // load c2pv transposed: c2sm[c*16+p] = c2r[p*16+c]; imag at +256
    for (int i = tid; i < 512; i += NTHREADS) {
        int v = i & 255;
        int p = v >> 4, c = v & 15;
        float val = (i < 256) ? c2r[i] : c2i[v];
        c2sm[(i < 256 ? 0 : 256) + c*16 + p] = val;
    }

    const float* xr = binsR + (size_t)bt * 4 * TF;
    const float* xi = binsI + (size_t)bt * 4 * TF;

    // ---------- phase 1: normalized covariance per bin ----------
    for (int f = tid; f < TF; f += NTHREADS) {
        float ar0 = xr[f],        ai0 = xi[f];
        float ar1 = xr[TF+f],     ai1 = xi[TF+f];
        float ar2 = xr[2*TF+f],   ai2 = xi[2*TF+f];
        float ar3 = xr[3*TF+f],   ai3 = xi[3*TF+f];
        float d0 = ar0*ar0 + ai0*ai0;
        float d1 = ar1*ar1 + ai1*ai1;
        float d2 = ar2*ar2 + ai2*ai2;
        float d3 = ar3*ar3 + ai3*ai3;
        float inv = 1.0f / fmaxf(d0+d1+d2+d3, 1e-20f);
        ((float2*)(covsm + 6*CST))[f] = make_float2(d0*inv, d1*inv);
        ((float2*)(covsm + 7*CST))[f] = make_float2(d2*inv, d3*inv);
#define PAIR(s, Ri, Ii, Rj, Ij) \
        ((float2*)(covsm + (s)*CST))[f] = \
            make_float2(((Ri)*(Rj) + (Ii)*(Ij))*inv, ((Ii)*(Rj) - (Ri)*(Ij))*inv);
        PAIR(0, ar0, ai0, ar1, ai1)
        PAIR(1, ar0, ai0, ar2, ai2)
        PAIR(2, ar0, ai0, ar3, ai3)
        PAIR(3, ar1, ai1, ar2, ai2)
        PAIR(4, ar1, ai1, ar3, ai3)
        PAIR(5, ar2, ai2, ar3, ai3)
#undef PAIR
    }
    __syncthreads();

    // ---------- phase 2: phase adjustment  adj = |cov| * z/|z|, z = conj(cov[lo])*cov[hi] ----------
    for (int f = tid; f < TF; f += NTHREADS) {
        int lo = (f == 0) ? 0 : ((f == TF-1) ? TF-3 : f-1);
        int hi = lo + 2;
        #pragma unroll
        for (int s = 0; s < 6; s++) {
            const float2* cs = (const float2*)(covsm + s*CST);
            float2 pc = cs[f];
            float2 lc = cs[lo];
            float2 hc = cs[hi];
            float zr = lc.x*hc.x + lc.y*hc.y;
            float zi = lc.x*hc.y - lc.y*hc.x;
            float m2 = pc.x*pc.x + pc.y*pc.y;
            float z2 = zr*zr + zi*zi;
            float aR, aI;
            if (z2 > 0.0f) {
                float sc = sqrtf(m2) * rsqrtf(z2);
                aR = sc*zr; aI = sc*zi;
            } else {
                aR = sqrtf(m2); aI = 0.0f;
            }
            ((float2*)(adjsm + s*CST))[f] = make_float2(aR, aI);
        }
        ((float2*)(adjsm + 6*CST))[f] = ((float2*)(covsm + 6*CST))[f];
        ((float2*)(adjsm + 7*CST))[f] = ((float2*)(covsm + 7*CST))[f];
    }
    __syncthreads();

    // ---------- phase 3: contraction over F (Hermitian-compact) ----------
    // thread = (kp, slot): kp in [0,24) covers k=2kp,2kp+1 ; slot in [0,8)
    const int kp   = tid >> 3;
    const int slot = tid & 7;
    float A0=0,A1=0,A2=0,A3=0,A4=0,A5=0,A6=0,A7=0;
    const float* aslot = adjsm + slot*CST;

    for (int tf0 = 0; tf0 < TF; tf0 += TILE) {
        int len = min(TILE, TF - tf0);
        __syncthreads();   // previous tile fully consumed
        for (int n = tid; n < len*NK; n += NTHREADS) {
            bsmR[n] = bandR[tf0*NK + n];
            bsmI[n] = bandI[tf0*NK + n];
        }
        __syncthreads();
        const float2* ap = (const float2*)(aslot + 2*tf0);
        #pragma unroll 4
        for (int i = 0; i < len; ++i) {
            float2 a  = ap[i];
            float2 br = *(const float2*)(bsmR + i*NK + 2*kp);
            float2 bi = *(const float2*)(bsmI + i*NK + 2*kp);
            A0 += a.x*br.x; A1 += a.x*bi.x; A2 += a.y*br.x; A3 += a.y*bi.x;
            A4 += a.x*br.y; A5 += a.x*bi.y; A6 += a.y*br.y; A7 += a.y*bi.y;
        }
    }
    __syncthreads();

    // ---------- phase 4: reconstruct bc (complex 16) per k into smem ----------
    // pair slot s -> (i,j): S1=A0 (aR*bR), S3=A1 (aR*bI), S4=A2 (aI*bR), S2=A3 (aI*bI)
    //   bc[i*4+j] = (S1-S2) + i(S3+S4);  bc[j*4+i] = (S1+S2) + i(S3-S4)
    // slot map: 0->(0,1) 1->(0,2) 2->(0,3) 3->(1,2) 4->(1,3) 5->(2,3)
    float* qsm = covsm;   // reuse: [k][32] = re[0..15], im[16..31]
    {
        int k0 = 2*kp;
        float* q0 = qsm + k0*32;
        float* q1 = q0 + 32;
        if (slot < 6) {
            int i = (slot < 3) ? 0 : ((slot < 5) ? 1 : 2);
            int j = (slot < 3) ? slot+1 : ((slot < 5) ? slot-1 : 3);
            int c1 = i*4 + j, c2 = j*4 + i;
            q0[c1] = A0 - A3; q0[16+c1] = A1 + A2;
            q0[c2] = A0 + A3; q0[16+c2] = A1 - A2;
            q1[c1] = A4 - A7; q1[16+c1] = A5 + A6;
            q1[c2] = A4 + A7; q1[16+c2] = A5 - A6;
        } else {
            int d  = (slot == 6) ? 0 : 2;
            int cA = d*5, cB = (d+1)*5;
            q0[cA] = A0; q0[16+cA] = A1; q0[cB] = A2; q0[16+cB] = A3;
            q1[cA] = A4; q1[16+cA] = A5; q1[cB] = A6; q1[16+cB] = A7;
        }
    }
    __syncthreads();

    // ---------- phase 5: per-k normalize + c2pv projection (real part), write out ----------
    // out layout (B, K, T, 16); IIR kernel runs over it in place.
    for (int o = tid; o < NK*16; o += NTHREADS) {
        int k = o >> 4, p = o & 15;
        const float* qk = qsm + k*32;
        float ds = fmaxf(qk[0] + qk[5] + qk[10] + qk[15], 1e-20f);
        float acc = 0.0f;
        #pragma unroll
        for (int c = 0; c < 16; c++) {
            acc += c2sm[c*16 + p] * qk[c];
            acc -= c2sm[256 + c*16 + p] * qk[16 + c];
        }
        out[(((size_t)b*NK + k)*1024 + t)*16 + p] = acc / ds;
    }
}

// ---------------- stage 2: in-place IIR over frames ----------------
// y_t = a*y_{t-1} + (1-a)*x_t,  a = exp(-10/tau_k). 3072 independent real series.
__global__ __launch_bounds__(64) void pv_iir(float* __restrict__ out,
                                             const float* __restrict__ tau)
{
    int idx = blockIdx.x * 64 + threadIdx.x;     // [0, 4*48*16)
    int p = idx & 15;
    int k = (idx >> 4) % NK;
    int b = idx / (NK*16);
    float a  = expf(-10.0f / tau[k]);
    float om = 1.0f - a;
    float* ptr = out + (((size_t)b*NK + k)*1024)*16 + p;
    float y = ptr[0];
    #pragma unroll 16
    for (int t = 1; t < 1024; ++t) {
        float x = ptr[t*16];
        y = a*y + om*x;
        ptr[t*16] = y;
    }
}

extern "C" void kernel_launch(void* const* d_in, const int* in_sizes, int n_in,
                              void* d_out, int out_size)
{
    const float* binsR = (const float*)d_in[0];
    const float* binsI = (const float*)d_in[1];
    const float* bandR = (const float*)d_in[2];
    const float* bandI = (const float*)d_in[3];
    const float* c2r   = (const float*)d_in[4];
    const float* c2i   = (const float*)d_in[5];
    const float* tau   = (const float*)d_in[6];
    float* out = (float*)d_out;

    size_t smem = SMEM_FLOATS * sizeof(float);   // ~106.6 KB
    cudaFuncSetAttribute(pv_stage1, cudaFuncAttributeMaxDynamicSharedMemorySize, (int)smem);

    pv_stage1<<<4096, NTHREADS, smem>>>(binsR, binsI, bandR, bandI, c2r, c2i, out);
    pv_iir<<<48, 64>>>(out, tau);
}

// round 4
// speedup vs baseline: 1.0497x; 1.0497x over previous
#include <cuda_runtime.h>
#include <math.h>

#define TF 481
#define NK 48
#define NTHREADS 192
#define TILE_F 124
#define CST 962            // 2*TF, float2-interleaved cov slot stride
#define ADJS 482           // adjT row stride (f-major rows), 16 rows
#define BROW 100           // bsm row floats (96 + 4 pad)

// smem map (floats)
#define OFF_COV   0                 // 8*CST = 7696
#define OFF_ADJT  7696              // 16*482 = 7712 -> 15408
#define OFF_BSM   15408             // 124*100 = 12400 -> 27808
#define OFF_C2    27808             // 512 -> 28320
#define SMEM_FLOATS 28320
// overlays (regions dead by the time these are written)
#define OFF_CPART 0                 // 4*16*100 = 6400  (over covsm)
#define OFF_CFIN  6400              // 16*100 = 1600 -> 8000
#define OFF_QSM   8000              // 48*32 = 1536 -> 9536

__device__ float g_bandint[TF * 96];   // [f][2k+c] interleaved band

// ---------------- prep: interleave band once ----------------
__global__ void pv_prep(const float* __restrict__ bandR, const float* __restrict__ bandI)
{
    int i = blockIdx.x * 256 + threadIdx.x;
    if (i < TF * 96) {
        int f = i / 96, j = i % 96;
        int k = j >> 1;
        g_bandint[i] = (j & 1) ? bandI[f * NK + k] : bandR[f * NK + k];
    }
}

// ---------------- stage 1 ----------------
__global__ __launch_bounds__(NTHREADS) void pv_stage1(
    const float* __restrict__ binsR, const float* __restrict__ binsI,
    const float* __restrict__ c2r,  const float* __restrict__ c2i,
    float* __restrict__ out)
{
    extern __shared__ float sm[];
    float* covsm = sm + OFF_COV;
    float* adjT  = sm + OFF_ADJT;   // adjT[c*ADJS + f], c in [0,16)
    float* bsm   = sm + OFF_BSM;    // bsm[fi*BROW + n], n in [0,96)
    float* c2sm  = sm + OFF_C2;

    const int bt  = blockIdx.x;
    const int tid = threadIdx.x;
    const int b   = bt >> 10;
    const int t   = bt & 1023;

    // c2pv transposed: c2sm[c*16+p] = c2r[p*16+c]; imag at +256
    for (int i = tid; i < 512; i += NTHREADS) {
        int v = i & 255;
        int p = v >> 4, c = v & 15;
        float val = (i < 256) ? c2r[i] : c2i[v];
        c2sm[(i < 256 ? 0 : 256) + c * 16 + p] = val;
    }

    const float* xr = binsR + (size_t)bt * 4 * TF;
    const float* xi = binsI + (size_t)bt * 4 * TF;

    // ---- phase 1: normalized covariance per bin (slot-major, float2) ----
    for (int f = tid; f < TF; f += NTHREADS) {
        float ar0 = xr[f],        ai0 = xi[f];
        float ar1 = xr[TF+f],     ai1 = xi[TF+f];
        float ar2 = xr[2*TF+f],   ai2 = xi[2*TF+f];
        float ar3 = xr[3*TF+f],   ai3 = xi[3*TF+f];
        float d0 = ar0*ar0 + ai0*ai0;
        float d1 = ar1*ar1 + ai1*ai1;
        float d2 = ar2*ar2 + ai2*ai2;
        float d3 = ar3*ar3 + ai3*ai3;
        float inv = 1.0f / fmaxf(d0+d1+d2+d3, 1e-20f);
        ((float2*)(covsm + 6*CST))[f] = make_float2(d0*inv, d1*inv);
        ((float2*)(covsm + 7*CST))[f] = make_float2(d2*inv, d3*inv);
#define PAIR(s, Ri, Ii, Rj, Ij) \
        ((float2*)(covsm + (s)*CST))[f] = \
            make_float2(((Ri)*(Rj) + (Ii)*(Ij))*inv, ((Ii)*(Rj) - (Ri)*(Ij))*inv);
        PAIR(0, ar0, ai0, ar1, ai1)
        PAIR(1, ar0, ai0, ar2, ai2)
        PAIR(2, ar0, ai0, ar3, ai3)
        PAIR(3, ar1, ai1, ar2, ai2)
        PAIR(4, ar1, ai1, ar3, ai3)
        PAIR(5, ar2, ai2, ar3, ai3)
#undef PAIR
    }
    __syncthreads();

    // ---- phase 2: phase adjust, write adjT column-major (c rows, f cols) ----
    {
        const int s  = tid % 6;
        const int f0 = tid / 6;            // [0,32)
        const float2* cs = (const float2*)(covsm + s * CST);
        float* rowR = adjT + (2*s)   * ADJS;
        float* rowI = adjT + (2*s+1) * ADJS;
        for (int f = f0; f < TF; f += 32) {
            int lo = (f == 0) ? 0 : ((f == TF-1) ? TF-3 : f-1);
            int hi = lo + 2;
            float2 pc = cs[f];
            float2 lc = cs[lo];
            float2 hc = cs[hi];
            float zr = lc.x*hc.x + lc.y*hc.y;
            float zi = lc.x*hc.y - lc.y*hc.x;
            float m2 = pc.x*pc.x + pc.y*pc.y;
            float z2 = zr*zr + zi*zi;
            float aR, aI;
            if (z2 > 0.0f) {
                float sc = sqrtf(m2) * rsqrtf(z2);
                aR = sc*zr; aI = sc*zi;
            } else {
                aR = sqrtf(m2); aI = 0.0f;
            }
            rowR[f] = aR;
            rowI[f] = aI;
        }
        // diagonals -> comps 12..15
        for (int n = tid; n < 4*TF; n += NTHREADS) {
            int d = n & 3, f = n >> 2;
            adjT[(12+d)*ADJS + f] = covsm[(6 + (d>>1))*CST + 2*f + (d&1)];
        }
    }
    __syncthreads();

    // ---- phase 3: C[16][96] = sum_f adjT[c][f] * bandint[f][n]  (register-tiled) ----
    // thread: g = tid&3 (f-split), tt = tid>>2: m2 = tt/24 (8 a-comps), n24 = tt%24 (4 b-comps)
    const int g   = tid & 3;
    const int tt  = tid >> 2;
    const int m2  = tt / 24;
    const int n24 = tt % 24;
    const float* aB = adjT + m2 * 8 * ADJS;

    float acc[8][4];
    #pragma unroll
    for (int u = 0; u < 8; u++)
        #pragma unroll
        for (int v = 0; v < 4; v++) acc[u][v] = 0.0f;

    for (int tf0 = 0; tf0 < TF; tf0 += TILE_F) {
        int len = min(TILE_F, TF - tf0);
        __syncthreads();
        for (int idx = tid; idx < len * 24; idx += NTHREADS) {
            int fi = idx / 24, j4 = idx % 24;
            *(float4*)&bsm[fi*BROW + j4*4] =
                *(const float4*)&g_bandint[(tf0+fi)*96 + j4*4];
        }
        __syncthreads();
        #pragma unroll 2
        for (int fi = g; fi < len; fi += 4) {
            int f = tf0 + fi;
            float a0 = aB[0*ADJS + f], a1 = aB[1*ADJS + f];
            float a2 = aB[2*ADJS + f], a3 = aB[3*ADJS + f];
            float a4 = aB[4*ADJS + f], a5 = aB[5*ADJS + f];
            float a6 = aB[6*ADJS + f], a7 = aB[7*ADJS + f];
            float4 bv = *(const float4*)&bsm[fi*BROW + n24*4];
#define ROW(u, av) \
            acc[u][0] += av*bv.x; acc[u][1] += av*bv.y; \
            acc[u][2] += av*bv.z; acc[u][3] += av*bv.w;
            ROW(0,a0) ROW(1,a1) ROW(2,a2) ROW(3,a3)
            ROW(4,a4) ROW(5,a5) ROW(6,a6) ROW(7,a7)
#undef ROW
        }
    }
    __syncthreads();

    // ---- reduce 4 f-partials ----
    float* Cpart = sm + OFF_CPART;
    float* Cfin  = sm + OFF_CFIN;
    #pragma unroll
    for (int u = 0; u < 8; u++) {
        int m = m2*8 + u;
        *(float4*)&Cpart[(g*16 + m)*BROW + n24*4] =
            make_float4(acc[u][0], acc[u][1], acc[u][2], acc[u][3]);
    }
    __syncthreads();
    for (int idx = tid; idx < 16*96; idx += NTHREADS) {
        int m = idx / 96, n = idx % 96;
        float s0 = Cpart[(0*16+m)*BROW + n] + Cpart[(1*16+m)*BROW + n]
                 + Cpart[(2*16+m)*BROW + n] + Cpart[(3*16+m)*BROW + n];
        Cfin[m*BROW + n] = s0;
    }
    __syncthreads();

    // ---- phase 4: reconstruct bc(complex 16) per k ----
    float* qsm = sm + OFF_QSM;      // [k][32]: re 0..15, im 16..31
    {
        const int kp   = tid >> 3;     // [0,24)
        const int slot = tid & 7;
        int m0 = (slot < 6) ? 2*slot : 12 + 2*(slot-6);
        float4 r0 = *(const float4*)&Cfin[m0*BROW + 4*kp];       // aR x (bR0,bI0,bR1,bI1)
        float4 r1 = *(const float4*)&Cfin[(m0+1)*BROW + 4*kp];   // aI x (...)
        float A0=r0.x, A1=r0.y, A4=r0.z, A5=r0.w;
        float A2=r1.x, A3=r1.y, A6=r1.z, A7=r1.w;
        float* q0 = qsm + (2*kp)*32;
        float* q1 = q0 + 32;
        if (slot < 6) {
            int i = (slot < 3) ? 0 : ((slot < 5) ? 1 : 2);
            int j = (slot < 3) ? slot+1 : ((slot < 5) ? slot-1 : 3);
            int c1 = i*4 + j, c2 = j*4 + i;
            q0[c1] = A0 - A3; q0[16+c1] = A1 + A2;
            q0[c2] = A0 + A3; q0[16+c2] = A1 - A2;
            q1[c1] = A4 - A7; q1[16+c1] = A5 + A6;
            q1[c2] = A4 + A7; q1[16+c2] = A5 - A6;
        } else {
            int d  = (slot == 6) ? 0 : 2;
            int cA = d*5, cB = (d+1)*5;
            q0[cA] = A0; q0[16+cA] = A1; q0[cB] = A2; q0[16+cB] = A3;
            q1[cA] = A4; q1[16+cA] = A5; q1[cB] = A6; q1[16+cB] = A7;
        }
    }
    __syncthreads();

    // ---- phase 5: normalize + c2pv projection (real part) ----
    for (int o = tid; o < NK*16; o += NTHREADS) {
        int k = o >> 4, p = o & 15;
        const float* qk = qsm + k*32;
        float ds = fmaxf(qk[0] + qk[5] + qk[10] + qk[15], 1e-20f);
        float acc2 = 0.0f;
        #pragma unroll
        for (int c = 0; c < 16; c++) {
            acc2 += c2sm[c*16 + p] * qk[c];
            acc2 -= c2sm[256 + c*16 + p] * qk[16 + c];
        }
        out[(((size_t)b*NK + k)*1024 + t)*16 + p] = acc2 / ds;
    }
}

// ---------------- stage 2: chunked parallel-scan IIR ----------------
// y_t = a*y_{t-1} + (1-a)*x_t, a = exp(-10/tau). 32 chunks x 32 steps per series.
__global__ __launch_bounds__(512) void pv_iir(float* __restrict__ out,
                                              const float* __restrict__ tau)
{
    __shared__ float tails[32*16];
    __shared__ float carry[32*16];
    const int bk  = blockIdx.x;          // b*NK + k
    const int k   = bk % NK;
    const int tid = threadIdx.x;
    const int chunk = tid >> 4, p = tid & 15;

    const float a  = expf(-10.0f / tau[k]);
    const float om = 1.0f - a;
    float* base = out + ((size_t)bk * 1024 + chunk * 32) * 16 + p;

    float x[32];
    #pragma unroll
    for (int j = 0; j < 32; j++) x[j] = base[j*16];

    float l[32];
    l[0] = (chunk == 0) ? x[0] : om * x[0];
    #pragma unroll
    for (int j = 1; j < 32; j++) l[j] = a*l[j-1] + om*x[j];

    tails[chunk*16 + p] = l[31];
    __syncthreads();

    if (tid < 16) {
        float A = expf(-320.0f / tau[k]);   // a^32
        float s = 0.0f;
        #pragma unroll
        for (int c = 0; c < 32; c++) {
            carry[c*16 + tid] = s;
            s = tails[c*16 + tid] + A * s;
        }
    }
    __syncthreads();

    float cin = carry[chunk*16 + p];
    float pw = a;
    #pragma unroll
    for (int j = 0; j < 32; j++) {
        base[j*16] = l[j] + pw * cin;
        pw *= a;
    }
}

extern "C" void kernel_launch(void* const* d_in, const int* in_sizes, int n_in,
                              void* d_out, int out_size)
{
    const float* binsR = (const float*)d_in[0];
    const float* binsI = (const float*)d_in[1];
    const float* bandR = (const float*)d_in[2];
    const float* bandI = (const float*)d_in[3];
    const float* c2r   = (const float*)d_in[4];
    const float* c2i   = (const float*)d_in[5];
    const float* tau   = (const float*)d_in[6];
    float* out = (float*)d_out;

    size_t smem = SMEM_FLOATS * sizeof(float);   // ~113 KB
    cudaFuncSetAttribute(pv_stage1, cudaFuncAttributeMaxDynamicSharedMemorySize, (int)smem);

    pv_prep<<<(TF*96 + 255)/256, 256>>>(bandR, bandI);
    pv_stage1<<<4096, NTHREADS, smem>>>(binsR, binsI, c2r, c2i, out);
    pv_iir<<<4*NK, 512>>>(out, tau);
}

// round 5
// speedup vs baseline: 1.4685x; 1.3990x over previous
#include <cuda_runtime.h>
#include <math.h>

#define TF 481
#define NK 48
#define NT 384
#define TILEF 64
#define ADJS 482           // adjT row stride
#define BROW 100           // 96 + 4 pad

// smem map (floats)
#define OFF_ADJT 0                       // 2*16*ADJS = 15424
#define OFF_BSM  15424                   // TILEF*BROW = 6400
#define OFF_C2   21824                   // 512
#define SMEMF    22336                   // 89.3 KB
// overlays (dead regions after GEMM)
#define OFF_CPART OFF_ADJT               // 2*6400 = 12800 over adjT
#define OFF_CF    OFF_BSM                // 2*1600 = 3200 over bsm
#define OFF_QSM   (OFF_BSM + 3200)      // 2*1536 = 3072 (<= bsm end)

__device__ float g_bandint[TF * 96];     // [f][2k+c] interleaved band

__global__ void pv_prep(const float* __restrict__ bandR, const float* __restrict__ bandI)
{
    int i = blockIdx.x * 256 + threadIdx.x;
    if (i < TF * 96) {
        int f = i / 96, j = i % 96;
        int k = j >> 1;
        g_bandint[i] = (j & 1) ? bandI[f * NK + k] : bandR[f * NK + k];
    }
}

// 6 unnormalized pair covariances x_i * conj(x_j) for (0,1)(0,2)(0,3)(1,2)(1,3)(2,3)
__device__ __forceinline__ void pairs6(const float* __restrict__ xr,
                                       const float* __restrict__ xi, int f,
                                       float* pr, float* pi)
{
    float r0 = xr[f],      i0 = xi[f];
    float r1 = xr[TF+f],   i1 = xi[TF+f];
    float r2 = xr[2*TF+f], i2 = xi[2*TF+f];
    float r3 = xr[3*TF+f], i3 = xi[3*TF+f];
#define PR(s,Ri,Ii,Rj,Ij) pr[s] = Ri*Rj + Ii*Ij; pi[s] = Ii*Rj - Ri*Ij;
    PR(0,r0,i0,r1,i1) PR(1,r0,i0,r2,i2) PR(2,r0,i0,r3,i3)
    PR(3,r1,i1,r2,i2) PR(4,r1,i1,r3,i3) PR(5,r2,i2,r3,i3)
#undef PR
}

// ---------------- stage 1: two frames per block ----------------
__global__ __launch_bounds__(NT) void pv_stage1(
    const float* __restrict__ binsR, const float* __restrict__ binsI,
    const float* __restrict__ c2r,  const float* __restrict__ c2i,
    float* __restrict__ out)
{
    extern __shared__ float sm[];
    float* adjT = sm + OFF_ADJT;   // [tl][c][f]
    float* bsm  = sm + OFF_BSM;
    float* c2sm = sm + OFF_C2;

    const int tid = threadIdx.x;
    const int bt0 = blockIdx.x * 2;
    const int b   = bt0 >> 10;
    const int t0  = bt0 & 1023;

    // c2pv transposed: c2sm[c*16+p] = c2r[p*16+c]; imag at +256
    for (int i = tid; i < 512; i += NT) {
        int v = i & 255;
        int p = v >> 4, c = v & 15;
        float val = (i < 256) ? c2r[i] : c2i[v];
        c2sm[(i < 256 ? 0 : 256) + c * 16 + p] = val;
    }

    // ---- fused phase 1+2: adjT directly from x (recompute neighbors) ----
    for (int u = tid; u < 2 * TF; u += NT) {
        int tl = 0, f = u;
        if (f >= TF) { f -= TF; tl = 1; }
        const float* xr = binsR + (size_t)(bt0 + tl) * 4 * TF;
        const float* xi = binsI + (size_t)(bt0 + tl) * 4 * TF;
        int lo = (f == 0) ? 0 : ((f == TF-1) ? TF-3 : f-1);
        int hi = lo + 2;

        // center: diagonals + inv
        float r0 = xr[f],      i0 = xi[f];
        float r1 = xr[TF+f],   i1 = xi[TF+f];
        float r2 = xr[2*TF+f], i2 = xi[2*TF+f];
        float r3 = xr[3*TF+f], i3 = xi[3*TF+f];
        float d0 = r0*r0 + i0*i0;
        float d1 = r1*r1 + i1*i1;
        float d2 = r2*r2 + i2*i2;
        float d3 = r3*r3 + i3*i3;
        float inv = 1.0f / fmaxf(d0+d1+d2+d3, 1e-20f);

        float pr[6], pi[6];
#define PR(s,Ri,Ii,Rj,Ij) pr[s] = Ri*Rj + Ii*Ij; pi[s] = Ii*Rj - Ri*Ij;
        PR(0,r0,i0,r1,i1) PR(1,r0,i0,r2,i2) PR(2,r0,i0,r3,i3)
        PR(3,r1,i1,r2,i2) PR(4,r1,i1,r3,i3) PR(5,r2,i2,r3,i3)
#undef PR
        float lr[6], li[6], hr[6], hi_[6];
        pairs6(xr, xi, lo, lr, li);
        pairs6(xr, xi, hi, hr, hi_);

        float* base = adjT + tl * 16 * ADJS;
        #pragma unroll
        for (int s = 0; s < 6; s++) {
            // angle of conj(c_lo)*c_hi is invariant to positive normalization
            float zr = lr[s]*hr[s] + li[s]*hi_[s];
            float zi = lr[s]*hi_[s] - li[s]*hr[s];
            float m  = sqrtf(pr[s]*pr[s] + pi[s]*pi[s]) * inv;   // |cov_norm|
            float z2 = zr*zr + zi*zi;
            float aR, aI;
            if (z2 > 0.0f) {
                float sc = m * rsqrtf(z2);
                aR = sc*zr; aI = sc*zi;
            } else {
                aR = m; aI = 0.0f;
            }
            base[(2*s)*ADJS + f]   = aR;
            base[(2*s+1)*ADJS + f] = aI;
        }
        base[12*ADJS + f] = d0*inv;
        base[13*ADJS + f] = d1*inv;
        base[14*ADJS + f] = d2*inv;
        base[15*ADJS + f] = d3*inv;
    }
    __syncthreads();

    // ---- GEMM: per-t group of 192 threads; shared band tile ----
    const int tl_g = (tid >= 192) ? 1 : 0;
    const int gtid = tid - tl_g * 192;
    const int g    = gtid & 3;
    const int tt   = gtid >> 2;
    const int m2   = tt / 24;
    const int n24  = tt % 24;
    const float* aB = adjT + tl_g * 16 * ADJS + m2 * 8 * ADJS;

    float acc[8][4];
    #pragma unroll
    for (int u2 = 0; u2 < 8; u2++)
        #pragma unroll
        for (int v = 0; v < 4; v++) acc[u2][v] = 0.0f;

    for (int tf0 = 0; tf0 < TF; tf0 += TILEF) {
        int len = min(TILEF, TF - tf0);
        __syncthreads();
        for (int idx = tid; idx < len * 24; idx += NT) {
            int fi = idx / 24, j4 = idx % 24;
            *(float4*)&bsm[fi*BROW + j4*4] =
                *(const float4*)&g_bandint[(tf0+fi)*96 + j4*4];
        }
        __syncthreads();
        #pragma unroll 2
        for (int fi = g; fi < len; fi += 4) {
            int f = tf0 + fi;
            float a0 = aB[0*ADJS + f], a1 = aB[1*ADJS + f];
            float a2 = aB[2*ADJS + f], a3 = aB[3*ADJS + f];
            float a4 = aB[4*ADJS + f], a5 = aB[5*ADJS + f];
            float a6 = aB[6*ADJS + f], a7 = aB[7*ADJS + f];
            float4 bv = *(const float4*)&bsm[fi*BROW + n24*4];
#define ROW(u, av) \
            acc[u][0] += av*bv.x; acc[u][1] += av*bv.y; \
            acc[u][2] += av*bv.z; acc[u][3] += av*bv.w;
            ROW(0,a0) ROW(1,a1) ROW(2,a2) ROW(3,a3)
            ROW(4,a4) ROW(5,a5) ROW(6,a6) ROW(7,a7)
#undef ROW
        }
    }
    __syncthreads();

    // ---- reduce 4 f-partials (Cpart over adjT, Cfin/qsm over bsm) ----
    float* Cpart = sm + OFF_CPART + tl_g * 6400;
    #pragma unroll
    for (int u2 = 0; u2 < 8; u2++) {
        int m = m2*8 + u2;
        *(float4*)&Cpart[(g*16 + m)*BROW + n24*4] =
            make_float4(acc[u2][0], acc[u2][1], acc[u2][2], acc[u2][3]);
    }
    __syncthreads();
    for (int idx = tid; idx < 2*16*96; idx += NT) {
        int tl = idx / 1536, r = idx % 1536;
        int m = r / 96, n = r % 96;
        const float* cp = sm + OFF_CPART + tl * 6400;
        float s0 = cp[(0*16+m)*BROW + n] + cp[(1*16+m)*BROW + n]
                 + cp[(2*16+m)*BROW + n] + cp[(3*16+m)*BROW + n];
        sm[OFF_CF + tl*1600 + m*BROW + n] = s0;
    }
    __syncthreads();

    // ---- phase 4: reconstruct bc(complex 16) per k ----
    float* Cfin = sm + OFF_CF  + tl_g * 1600;
    float* qsm  = sm + OFF_QSM + tl_g * 1536;   // [k][32]: re 0..15, im 16..31
    {
        const int kp   = gtid >> 3;     // [0,24)
        const int slot = gtid & 7;
        int m0 = (slot < 6) ? 2*slot : 12 + 2*(slot-6);
        float4 rA = *(const float4*)&Cfin[m0*BROW + 4*kp];       // aR x (bR0,bI0,bR1,bI1)
        float4 rB = *(const float4*)&Cfin[(m0+1)*BROW + 4*kp];   // aI x (...)
        float A0=rA.x, A1=rA.y, A4=rA.z, A5=rA.w;
        float A2=rB.x, A3=rB.y, A6=rB.z, A7=rB.w;
        float* q0 = qsm + (2*kp)*32;
        float* q1 = q0 + 32;
        if (slot < 6) {
            int i = (slot < 3) ? 0 : ((slot < 5) ? 1 : 2);
            int j = (slot < 3) ? slot+1 : ((slot < 5) ? slot-1 : 3);
            int c1 = i*4 + j, c2 = j*4 + i;
            q0[c1] = A0 - A3; q0[16+c1] = A1 + A2;
            q0[c2] = A0 + A3; q0[16+c2] = A1 - A2;
            q1[c1] = A4 - A7; q1[16+c1] = A5 + A6;
            q1[c2] = A4 + A7; q1[16+c2] = A5 - A6;
        } else {
            int d  = (slot == 6) ? 0 : 2;
            int cA = d*5, cB = (d+1)*5;
            q0[cA] = A0; q0[16+cA] = A1; q0[cB] = A2; q0[16+cB] = A3;
            q1[cA] = A4; q1[16+cA] = A5; q1[cB] = A6; q1[16+cB] = A7;
        }
    }
    __syncthreads();

    // ---- phase 5: normalize + c2pv projection (real part) ----
    {
        const int t = t0 + tl_g;
        for (int o = gtid; o < NK*16; o += 192) {
            int k = o >> 4, p = o & 15;
            const float* qk = qsm + k*32;
            float ds = fmaxf(qk[0] + qk[5] + qk[10] + qk[15], 1e-20f);
            float acc2 = 0.0f;
            #pragma unroll
            for (int c = 0; c < 16; c++) {
                acc2 += c2sm[c*16 + p] * qk[c];
                acc2 -= c2sm[256 + c*16 + p] * qk[16 + c];
            }
            out[(((size_t)b*NK + k)*1024 + t)*16 + p] = acc2 / ds;
        }
    }
}

// ---------------- stage 2: chunked parallel-scan IIR ----------------
__global__ __launch_bounds__(512) void pv_iir(float* __restrict__ out,
                                              const float* __restrict__ tau)
{
    __shared__ float tails[32*16];
    __shared__ float carry[32*16];
    const int bk  = blockIdx.x;          // b*NK + k
    const int k   = bk % NK;
    const int tid = threadIdx.x;
    const int chunk = tid >> 4, p = tid & 15;

    const float a  = expf(-10.0f / tau[k]);
    const float om = 1.0f - a;
    float* base = out + ((size_t)bk * 1024 + chunk * 32) * 16 + p;

    float x[32];
    #pragma unroll
    for (int j = 0; j < 32; j++) x[j] = base[j*16];

    float l[32];
    l[0] = (chunk == 0) ? x[0] : om * x[0];
    #pragma unroll
    for (int j = 1; j < 32; j++) l[j] = a*l[j-1] + om*x[j];

    tails[chunk*16 + p] = l[31];
    __syncthreads();

    if (tid < 16) {
        float A = expf(-320.0f / tau[k]);   // a^32
        float s = 0.0f;
        #pragma unroll
        for (int c = 0; c < 32; c++) {
            carry[c*16 + tid] = s;
            s = tails[c*16 + tid] + A * s;
        }
    }
    __syncthreads();

    float cin = carry[chunk*16 + p];
    float pw = a;
    #pragma unroll
    for (int j = 0; j < 32; j++) {
        base[j*16] = l[j] + pw * cin;
        pw *= a;
    }
}

extern "C" void kernel_launch(void* const* d_in, const int* in_sizes, int n_in,
                              void* d_out, int out_size)
{
    const float* binsR = (const float*)d_in[0];
    const float* binsI = (const float*)d_in[1];
    const float* bandR = (const float*)d_in[2];
    const float* bandI = (const float*)d_in[3];
    const float* c2r   = (const float*)d_in[4];
    const float* c2i   = (const float*)d_in[5];
    const float* tau   = (const float*)d_in[6];
    float* out = (float*)d_out;

    size_t smem = SMEMF * sizeof(float);   // ~89.3 KB
    cudaFuncSetAttribute(pv_stage1, cudaFuncAttributeMaxDynamicSharedMemorySize, (int)smem);

    pv_prep<<<(TF*96 + 255)/256, 256>>>(bandR, bandI);
    pv_stage1<<<2048, NT, smem>>>(binsR, binsI, c2r, c2i, out);
    pv_iir<<<4*NK, 512>>>(out, tau);
}